// round 3
// baseline (speedup 1.0000x reference)
#include <cuda_runtime.h>
#include <cstdint>

#define B   32
#define HKV 8
#define G   4
#define HD  128
#define D   4096
#define NQ  4096
#define NKV 1024
#define NTOT 6144
#define L   2048
#define KSPLIT 8
#define NSPLIT 4

__device__ float g_qkv_part[KSPLIT * B * NTOT];
__device__ float g_qkv[B * NTOT];
__device__ float g_att_part[B * HKV * NSPLIT * G * HD];
__device__ float g_att_s[B * HKV * NSPLIT * G];
__device__ float g_attn[B * NQ];
__device__ float g_out_part[KSPLIT * B * D];

// -------------------- f32x2 packed FMA --------------------
__device__ __forceinline__ void fma2(unsigned long long& acc, unsigned long long a,
                                     unsigned long long b) {
    asm("fma.rn.f32x2 %0, %1, %2, %0;" : "+l"(acc) : "l"(a), "l"(b));
}
__device__ __forceinline__ float2 unpack2(unsigned long long v) {
    float2 f;
    asm("mov.b64 {%0, %1}, %2;" : "=f"(f.x), "=f"(f.y) : "l"(v));
    return f;
}

// -------------------- double-buffered GEMM core, MOV-free inner loop ---------
// C[32 x 128 tile] = A[32, k0:k0+512] * W[k0:k0+512, tile]; 256 thr; BK=32.
// As stored as duplicated float2 pairs {a,a}: LDS.128 -> two ready dup operands.
// Ws loaded as ulonglong2: LDS.128 -> two ready packed-pair operands.
__device__ __forceinline__ void gemm_core(
    const float* __restrict__ A,
    const float* __restrict__ W,
    int ldw, int wc0,
    float* __restrict__ C, int ldc,
    int k0)
{
    __shared__ __align__(16) float2 As2[2][32][34];   // pad 34: conflict-free STS.64
    __shared__ __align__(16) float  Ws[2][32][132];   // pad 132: conflict-free STS/LDS.128

    const int tid = threadIdx.x;
    const int tx = tid & 31;
    const int ty = tid >> 5;

    const int a_b = tid >> 3;
    const int a_k = (tid & 7) << 2;
    const int w_r = tid >> 3;
    const int w_c = (tid & 7) << 2;

    unsigned long long acc[4][2];
#pragma unroll
    for (int r = 0; r < 4; r++) { acc[r][0] = 0ull; acc[r][1] = 0ull; }

    // prefetch tile 0
    float4 av = *reinterpret_cast<const float4*>(A + a_b * 4096 + k0 + a_k);
    const float* wrow = W + (size_t)(k0 + w_r) * ldw + wc0 + w_c;
    float4 w0 = *reinterpret_cast<const float4*>(wrow);
    float4 w1 = *reinterpret_cast<const float4*>(wrow + 32);
    float4 w2 = *reinterpret_cast<const float4*>(wrow + 64);
    float4 w3 = *reinterpret_cast<const float4*>(wrow + 96);
    As2[0][a_k + 0][a_b] = make_float2(av.x, av.x);
    As2[0][a_k + 1][a_b] = make_float2(av.y, av.y);
    As2[0][a_k + 2][a_b] = make_float2(av.z, av.z);
    As2[0][a_k + 3][a_b] = make_float2(av.w, av.w);
    *reinterpret_cast<float4*>(&Ws[0][w_r][w_c])      = w0;
    *reinterpret_cast<float4*>(&Ws[0][w_r][w_c + 32]) = w1;
    *reinterpret_cast<float4*>(&Ws[0][w_r][w_c + 64]) = w2;
    *reinterpret_cast<float4*>(&Ws[0][w_r][w_c + 96]) = w3;
    __syncthreads();

    for (int kt = 0; kt < 16; kt++) {
        const int cur = kt & 1;
        float4 av2 = make_float4(0.f, 0.f, 0.f, 0.f);
        float4 w0n = av2, w1n = av2, w2n = av2, w3n = av2;
        if (kt < 15) {
            const int kg = k0 + (kt + 1) * 32;
            av2 = *reinterpret_cast<const float4*>(A + a_b * 4096 + kg + a_k);
            const float* wr2 = W + (size_t)(kg + w_r) * ldw + wc0 + w_c;
            w0n = *reinterpret_cast<const float4*>(wr2);
            w1n = *reinterpret_cast<const float4*>(wr2 + 32);
            w2n = *reinterpret_cast<const float4*>(wr2 + 64);
            w3n = *reinterpret_cast<const float4*>(wr2 + 96);
        }

#pragma unroll
        for (int k = 0; k < 32; k++) {
            ulonglong2 bv  = *reinterpret_cast<const ulonglong2*>(&Ws[cur][k][tx << 2]);
            ulonglong2 a01 = *reinterpret_cast<const ulonglong2*>(&As2[cur][k][ty << 2]);
            ulonglong2 a23 = *reinterpret_cast<const ulonglong2*>(&As2[cur][k][(ty << 2) + 2]);
            fma2(acc[0][0], a01.x, bv.x); fma2(acc[0][1], a01.x, bv.y);
            fma2(acc[1][0], a01.y, bv.x); fma2(acc[1][1], a01.y, bv.y);
            fma2(acc[2][0], a23.x, bv.x); fma2(acc[2][1], a23.x, bv.y);
            fma2(acc[3][0], a23.y, bv.x); fma2(acc[3][1], a23.y, bv.y);
        }

        if (kt < 15) {
            const int nb = cur ^ 1;
            As2[nb][a_k + 0][a_b] = make_float2(av2.x, av2.x);
            As2[nb][a_k + 1][a_b] = make_float2(av2.y, av2.y);
            As2[nb][a_k + 2][a_b] = make_float2(av2.z, av2.z);
            As2[nb][a_k + 3][a_b] = make_float2(av2.w, av2.w);
            *reinterpret_cast<float4*>(&Ws[nb][w_r][w_c])      = w0n;
            *reinterpret_cast<float4*>(&Ws[nb][w_r][w_c + 32]) = w1n;
            *reinterpret_cast<float4*>(&Ws[nb][w_r][w_c + 64]) = w2n;
            *reinterpret_cast<float4*>(&Ws[nb][w_r][w_c + 96]) = w3n;
        }
        __syncthreads();
    }

#pragma unroll
    for (int r = 0; r < 4; r++) {
        float2 lo = unpack2(acc[r][0]);
        float2 hi = unpack2(acc[r][1]);
        float4 o;
        o.x = lo.x; o.y = lo.y; o.z = hi.x; o.w = hi.y;
        *reinterpret_cast<float4*>(C + (size_t)((ty << 2) + r) * ldc + (tx << 2)) = o;
    }
}

__global__ void __launch_bounds__(256)
gemm_qkv_kernel(const float* __restrict__ x, const float* __restrict__ wq,
                const float* __restrict__ wk, const float* __restrict__ wv)
{
    const int col0 = blockIdx.x << 7;
    const int ks = blockIdx.y;
    const float* W; int ldw, wc0;
    if (col0 < NQ)            { W = wq; ldw = NQ;  wc0 = col0; }
    else if (col0 < NQ + NKV) { W = wk; ldw = NKV; wc0 = col0 - NQ; }
    else                      { W = wv; ldw = NKV; wc0 = col0 - NQ - NKV; }
    gemm_core(x, W, ldw, wc0,
              g_qkv_part + (size_t)ks * B * NTOT + col0, NTOT, ks * 512);
}

__global__ void __launch_bounds__(256)
gemm_wo_kernel(const float* __restrict__ wo)
{
    const int col0 = blockIdx.x << 7;
    const int ks = blockIdx.y;
    gemm_core(g_attn, wo, D, col0,
              g_out_part + (size_t)ks * B * D + col0, D, ks * 512);
}

// -------------------- split-K reduce + RoPE (float4, 2 slices) --------------
__global__ void __launch_bounds__(256)
rope_reduce_kernel(const float* __restrict__ fc, const float* __restrict__ fs,
                   int part)
{
    const int HALF = B * (NTOT / 4) / 2;   // float4 units per slice
    int idx = part * HALF + blockIdx.x * blockDim.x + threadIdx.x;
    int b = idx / (NTOT / 4);
    int col = (idx - b * (NTOT / 4)) * 4;
    const float* p = g_qkv_part + (size_t)b * NTOT + col;
    float4 e = make_float4(0.f, 0.f, 0.f, 0.f);
#pragma unroll
    for (int s = 0; s < KSPLIT; s++) {
        float4 a = *reinterpret_cast<const float4*>(p + (size_t)s * B * NTOT);
        e.x += a.x; e.y += a.y; e.z += a.z; e.w += a.w;
    }
    if (col < NQ + NKV) {
        int i = (col & (HD - 1)) >> 1;
        float c0 = fc[i], s0 = fs[i];
        float c1 = fc[i + 1], s1 = fs[i + 1];
        float4 r;
        r.x = e.x * c0 - e.y * s0;
        r.y = e.x * s0 + e.y * c0;
        r.z = e.z * c1 - e.w * s1;
        r.w = e.z * s1 + e.w * c1;
        e = r;
    }
    *reinterpret_cast<float4*>(g_qkv + (size_t)b * NTOT + col) = e;
}

// -------------------- attention: flash-decode, depth-2 prefetch -------------
__global__ void __launch_bounds__(256)
attn_kernel(const float* __restrict__ cache_k, const float* __restrict__ cache_v)
{
    const int blk = blockIdx.x;
    const int split = blk & (NSPLIT - 1);
    const int hkv = (blk >> 2) & (HKV - 1);
    const int b = blk >> 5;
    const int tid = threadIdx.x;
    const int w = tid >> 5;
    const int lane = tid & 31;

    const float scale = 0.08838834764831845f;
    float4 qf[G];
#pragma unroll
    for (int g = 0; g < G; g++) {
        int h = hkv * G + g;
        float4 q = *reinterpret_cast<const float4*>(g_qkv + (size_t)b * NTOT + h * HD + lane * 4);
        q.x *= scale; q.y *= scale; q.z *= scale; q.w *= scale;
        qf[g] = q;
    }

    float acc[G][4];
    float ssum[G];
#pragma unroll
    for (int g = 0; g < G; g++) {
        ssum[g] = 0.f;
        acc[g][0] = acc[g][1] = acc[g][2] = acc[g][3] = 0.f;
    }

    auto process = [&](float4 kf, float4 vf) {
        float p[G];
#pragma unroll
        for (int g = 0; g < G; g++)
            p[g] = qf[g].x * kf.x + qf[g].y * kf.y + qf[g].z * kf.z + qf[g].w * kf.w;
#pragma unroll
        for (int off = 16; off > 0; off >>= 1) {
#pragma unroll
            for (int g = 0; g < G; g++)
                p[g] += __shfl_xor_sync(0xffffffffu, p[g], off);
        }
#pragma unroll
        for (int g = 0; g < G; g++) {
            float e = __expf(p[g]);
            ssum[g] += e;
            acc[g][0] += e * vf.x;
            acc[g][1] += e * vf.y;
            acc[g][2] += e * vf.z;
            acc[g][3] += e * vf.w;
        }
    };

    const size_t bh = (size_t)(b * HKV + hkv) * L * HD;
    const int base = split * (L / NSPLIT) + w;
    const bool last_warp = (split == NSPLIT - 1) && (w == 7);
    const int niter = last_warp ? 63 : 64;

    const float* kcur = cache_k + bh + (size_t)base * HD + 4 * lane;
    const float* vcur = cache_v + bh + (size_t)base * HD + 4 * lane;

    // depth-2 software pipeline
    float4 k0f = *reinterpret_cast<const float4*>(kcur);
    float4 v0f = *reinterpret_cast<const float4*>(vcur);
    float4 k1f = make_float4(0.f, 0.f, 0.f, 0.f), v1f = k1f;
    if (niter > 1) {
        k1f = *reinterpret_cast<const float4*>(kcur + 8 * HD);
        v1f = *reinterpret_cast<const float4*>(vcur + 8 * HD);
    }
    for (int i = 0; i < niter; i++) {
        float4 kn = make_float4(0.f, 0.f, 0.f, 0.f), vn = kn;
        if (i + 2 < niter) {
            kn = *reinterpret_cast<const float4*>(kcur + 16 * HD);
            vn = *reinterpret_cast<const float4*>(vcur + 16 * HD);
        }
        kcur += 8 * HD;
        vcur += 8 * HD;
        process(k0f, v0f);
        k0f = k1f; v0f = v1f;
        k1f = kn;  v1f = vn;
    }
    if (last_warp) {
        float4 k2 = *reinterpret_cast<const float4*>(
            g_qkv + (size_t)b * NTOT + NQ + hkv * HD + 4 * lane);
        float4 v2 = *reinterpret_cast<const float4*>(
            g_qkv + (size_t)b * NTOT + NQ + NKV + hkv * HD + 4 * lane);
        process(k2, v2);
    }

    __shared__ __align__(16) float sm_acc[8][G * HD];
    __shared__ float sm_s[8][G];
#pragma unroll
    for (int g = 0; g < G; g++) {
        float4 o; o.x = acc[g][0]; o.y = acc[g][1]; o.z = acc[g][2]; o.w = acc[g][3];
        *reinterpret_cast<float4*>(&sm_acc[w][g * HD + lane * 4]) = o;
    }
    if (lane == 0) {
        sm_s[w][0] = ssum[0]; sm_s[w][1] = ssum[1];
        sm_s[w][2] = ssum[2]; sm_s[w][3] = ssum[3];
    }
    __syncthreads();

    for (int e = tid; e < G * HD; e += 256) {
        float v = 0.f;
#pragma unroll
        for (int ww = 0; ww < 8; ww++) v += sm_acc[ww][e];
        g_att_part[(size_t)blk * (G * HD) + e] = v;
    }
    if (tid < G) {
        float v = 0.f;
#pragma unroll
        for (int ww = 0; ww < 8; ww++) v += sm_s[ww][tid];
        g_att_s[blk * G + tid] = v;
    }
}

__global__ void __launch_bounds__(128)
attn_combine_kernel()
{
    const int p = blockIdx.x;
    const int b = p >> 3;
    const int hkv = p & (HKV - 1);
    const int t = threadIdx.x;
    const int g = t >> 5;
    float4 v = make_float4(0.f, 0.f, 0.f, 0.f);
    float s = 0.f;
#pragma unroll
    for (int sp = 0; sp < NSPLIT; sp++) {
        int blk = p * NSPLIT + sp;
        float4 a = *reinterpret_cast<const float4*>(
            g_att_part + (size_t)blk * (G * HD) + t * 4);
        v.x += a.x; v.y += a.y; v.z += a.z; v.w += a.w;
        s += g_att_s[blk * G + g];
    }
    float inv = 1.f / s;
    v.x *= inv; v.y *= inv; v.z *= inv; v.w *= inv;
    *reinterpret_cast<float4*>(g_attn + (size_t)b * NQ + hkv * (G * HD) + t * 4) = v;
}

__global__ void __launch_bounds__(256)
out_reduce_kernel(float* __restrict__ out)
{
    int idx = blockIdx.x * blockDim.x + threadIdx.x;
    float4 v = make_float4(0.f, 0.f, 0.f, 0.f);
#pragma unroll
    for (int s = 0; s < KSPLIT; s++) {
        float4 a = *reinterpret_cast<const float4*>(
            g_out_part + (size_t)s * B * D + idx * 4);
        v.x += a.x; v.y += a.y; v.z += a.z; v.w += a.w;
    }
    *reinterpret_cast<float4*>(out + (size_t)idx * 4) = v;
}

// -------------------- launch (attn at index 3 for the profiler) -------------
extern "C" void kernel_launch(void* const* d_in, const int* in_sizes, int n_in,
                              void* d_out, int out_size)
{
    const float* x  = (const float*)d_in[0];
    const float* ck = (const float*)d_in[1];
    const float* cv = (const float*)d_in[2];
    const float* wq = (const float*)d_in[3];
    const float* wk = (const float*)d_in[4];
    const float* wv = (const float*)d_in[5];
    const float* wo = (const float*)d_in[6];
    const float* fc = (const float*)d_in[7];
    const float* fs = (const float*)d_in[8];
    float* out = (float*)d_out;

    dim3 gq(NTOT / 128, KSPLIT);
    gemm_qkv_kernel<<<gq, 256>>>(x, wq, wk, wv);                   // idx 0

    const int HALF = B * (NTOT / 4) / 2;                           // 24576
    rope_reduce_kernel<<<HALF / 256, 256>>>(fc, fs, 0);            // idx 1
    rope_reduce_kernel<<<HALF / 256, 256>>>(fc, fs, 1);            // idx 2

    attn_kernel<<<B * HKV * NSPLIT, 256>>>(ck, cv);                // idx 3 (profiled)

    attn_combine_kernel<<<B * HKV, 128>>>();                       // idx 4

    dim3 gw(D / 128, KSPLIT);
    gemm_wo_kernel<<<gw, 256>>>(wo);                               // idx 5

    out_reduce_kernel<<<(B * D / 4) / 256, 256>>>(out);            // idx 6
}

// round 4
// speedup vs baseline: 1.0952x; 1.0952x over previous
#include <cuda_runtime.h>
#include <cstdint>

#define B   32
#define HKV 8
#define G   4
#define HD  128
#define D   4096
#define NQ  4096
#define NKV 1024
#define NTOT 6144
#define L   2048
#define KSPLIT 8
#define NSPLIT 2

__device__ float g_qkv_part[KSPLIT * B * NTOT];
__device__ float g_qkv[B * NTOT];
__device__ float g_att_part[B * HKV * NSPLIT * G * HD];
__device__ float g_att_s[B * HKV * NSPLIT * G];
__device__ float g_attn[B * NQ];
__device__ float g_out_part[KSPLIT * B * D];

// -------------------- f32x2 packed helpers --------------------
__device__ __forceinline__ unsigned long long pack2(float lo, float hi) {
    unsigned long long r;
    asm("mov.b64 %0, {%1, %2};" : "=l"(r) : "f"(lo), "f"(hi));
    return r;
}
__device__ __forceinline__ unsigned long long mul2(unsigned long long a,
                                                   unsigned long long b) {
    unsigned long long r;
    asm("mul.rn.f32x2 %0, %1, %2;" : "=l"(r) : "l"(a), "l"(b));
    return r;
}
__device__ __forceinline__ void fma2(unsigned long long& acc, unsigned long long a,
                                     unsigned long long b) {
    asm("fma.rn.f32x2 %0, %1, %2, %0;" : "+l"(acc) : "l"(a), "l"(b));
}
__device__ __forceinline__ float2 unpack2(unsigned long long v) {
    float2 f;
    asm("mov.b64 {%0, %1}, %2;" : "=f"(f.x), "=f"(f.y) : "l"(v));
    return f;
}

// -------------------- double-buffered GEMM core (unchanged from R3) ----------
__device__ __forceinline__ void gemm_core(
    const float* __restrict__ A,
    const float* __restrict__ W,
    int ldw, int wc0,
    float* __restrict__ C, int ldc,
    int k0)
{
    __shared__ __align__(16) float2 As2[2][32][34];
    __shared__ __align__(16) float  Ws[2][32][132];

    const int tid = threadIdx.x;
    const int tx = tid & 31;
    const int ty = tid >> 5;

    const int a_b = tid >> 3;
    const int a_k = (tid & 7) << 2;
    const int w_r = tid >> 3;
    const int w_c = (tid & 7) << 2;

    unsigned long long acc[4][2];
#pragma unroll
    for (int r = 0; r < 4; r++) { acc[r][0] = 0ull; acc[r][1] = 0ull; }

    float4 av = *reinterpret_cast<const float4*>(A + a_b * 4096 + k0 + a_k);
    const float* wrow = W + (size_t)(k0 + w_r) * ldw + wc0 + w_c;
    float4 w0 = *reinterpret_cast<const float4*>(wrow);
    float4 w1 = *reinterpret_cast<const float4*>(wrow + 32);
    float4 w2 = *reinterpret_cast<const float4*>(wrow + 64);
    float4 w3 = *reinterpret_cast<const float4*>(wrow + 96);
    As2[0][a_k + 0][a_b] = make_float2(av.x, av.x);
    As2[0][a_k + 1][a_b] = make_float2(av.y, av.y);
    As2[0][a_k + 2][a_b] = make_float2(av.z, av.z);
    As2[0][a_k + 3][a_b] = make_float2(av.w, av.w);
    *reinterpret_cast<float4*>(&Ws[0][w_r][w_c])      = w0;
    *reinterpret_cast<float4*>(&Ws[0][w_r][w_c + 32]) = w1;
    *reinterpret_cast<float4*>(&Ws[0][w_r][w_c + 64]) = w2;
    *reinterpret_cast<float4*>(&Ws[0][w_r][w_c + 96]) = w3;
    __syncthreads();

    for (int kt = 0; kt < 16; kt++) {
        const int cur = kt & 1;
        float4 av2 = make_float4(0.f, 0.f, 0.f, 0.f);
        float4 w0n = av2, w1n = av2, w2n = av2, w3n = av2;
        if (kt < 15) {
            const int kg = k0 + (kt + 1) * 32;
            av2 = *reinterpret_cast<const float4*>(A + a_b * 4096 + kg + a_k);
            const float* wr2 = W + (size_t)(kg + w_r) * ldw + wc0 + w_c;
            w0n = *reinterpret_cast<const float4*>(wr2);
            w1n = *reinterpret_cast<const float4*>(wr2 + 32);
            w2n = *reinterpret_cast<const float4*>(wr2 + 64);
            w3n = *reinterpret_cast<const float4*>(wr2 + 96);
        }

#pragma unroll
        for (int k = 0; k < 32; k++) {
            ulonglong2 bv  = *reinterpret_cast<const ulonglong2*>(&Ws[cur][k][tx << 2]);
            ulonglong2 a01 = *reinterpret_cast<const ulonglong2*>(&As2[cur][k][ty << 2]);
            ulonglong2 a23 = *reinterpret_cast<const ulonglong2*>(&As2[cur][k][(ty << 2) + 2]);
            fma2(acc[0][0], a01.x, bv.x); fma2(acc[0][1], a01.x, bv.y);
            fma2(acc[1][0], a01.y, bv.x); fma2(acc[1][1], a01.y, bv.y);
            fma2(acc[2][0], a23.x, bv.x); fma2(acc[2][1], a23.x, bv.y);
            fma2(acc[3][0], a23.y, bv.x); fma2(acc[3][1], a23.y, bv.y);
        }

        if (kt < 15) {
            const int nb = cur ^ 1;
            As2[nb][a_k + 0][a_b] = make_float2(av2.x, av2.x);
            As2[nb][a_k + 1][a_b] = make_float2(av2.y, av2.y);
            As2[nb][a_k + 2][a_b] = make_float2(av2.z, av2.z);
            As2[nb][a_k + 3][a_b] = make_float2(av2.w, av2.w);
            *reinterpret_cast<float4*>(&Ws[nb][w_r][w_c])      = w0n;
            *reinterpret_cast<float4*>(&Ws[nb][w_r][w_c + 32]) = w1n;
            *reinterpret_cast<float4*>(&Ws[nb][w_r][w_c + 64]) = w2n;
            *reinterpret_cast<float4*>(&Ws[nb][w_r][w_c + 96]) = w3n;
        }
        __syncthreads();
    }

#pragma unroll
    for (int r = 0; r < 4; r++) {
        float2 lo = unpack2(acc[r][0]);
        float2 hi = unpack2(acc[r][1]);
        float4 o;
        o.x = lo.x; o.y = lo.y; o.z = hi.x; o.w = hi.y;
        *reinterpret_cast<float4*>(C + (size_t)((ty << 2) + r) * ldc + (tx << 2)) = o;
    }
}

__global__ void __launch_bounds__(256)
gemm_qkv_kernel(const float* __restrict__ x, const float* __restrict__ wq,
                const float* __restrict__ wk, const float* __restrict__ wv)
{
    const int col0 = blockIdx.x << 7;
    const int ks = blockIdx.y;
    const float* W; int ldw, wc0;
    if (col0 < NQ)            { W = wq; ldw = NQ;  wc0 = col0; }
    else if (col0 < NQ + NKV) { W = wk; ldw = NKV; wc0 = col0 - NQ; }
    else                      { W = wv; ldw = NKV; wc0 = col0 - NQ - NKV; }
    gemm_core(x, W, ldw, wc0,
              g_qkv_part + (size_t)ks * B * NTOT + col0, NTOT, ks * 512);
}

__global__ void __launch_bounds__(256)
gemm_wo_kernel(const float* __restrict__ wo)
{
    const int col0 = blockIdx.x << 7;
    const int ks = blockIdx.y;
    gemm_core(g_attn, wo, D, col0,
              g_out_part + (size_t)ks * B * D + col0, D, ks * 512);
}

// -------------------- split-K reduce + RoPE (float4, 2 slices) --------------
__global__ void __launch_bounds__(256)
rope_reduce_kernel(const float* __restrict__ fc, const float* __restrict__ fs,
                   int part)
{
    const int HALF = B * (NTOT / 4) / 2;
    int idx = part * HALF + blockIdx.x * blockDim.x + threadIdx.x;
    int b = idx / (NTOT / 4);
    int col = (idx - b * (NTOT / 4)) * 4;
    const float* p = g_qkv_part + (size_t)b * NTOT + col;
    float4 e = make_float4(0.f, 0.f, 0.f, 0.f);
#pragma unroll
    for (int s = 0; s < KSPLIT; s++) {
        float4 a = *reinterpret_cast<const float4*>(p + (size_t)s * B * NTOT);
        e.x += a.x; e.y += a.y; e.z += a.z; e.w += a.w;
    }
    if (col < NQ + NKV) {
        int i = (col & (HD - 1)) >> 1;
        float c0 = fc[i], s0 = fs[i];
        float c1 = fc[i + 1], s1 = fs[i + 1];
        float4 r;
        r.x = e.x * c0 - e.y * s0;
        r.y = e.x * s0 + e.y * c0;
        r.z = e.z * c1 - e.w * s1;
        r.w = e.z * s1 + e.w * c1;
        e = r;
    }
    *reinterpret_cast<float4*>(g_qkv + (size_t)b * NTOT + col) = e;
}

// -------------------- attention: low-issue flash-decode ---------------------
// grid = B*HKV*NSPLIT (512). Warp-per-key; lane owns dims 4L..4L+3.
// Reduce: butterfly(16,8) on 4 scores -> select by lane group -> butterfly(4,2,1)
// -> ONE exp per lane -> index-shuffle broadcast. Packed f32x2 dot & PV.
__global__ void __launch_bounds__(256, 4)
attn_kernel(const float* __restrict__ cache_k, const float* __restrict__ cache_v)
{
    const int blk = blockIdx.x;
    const int split = blk & (NSPLIT - 1);
    const int hkv = (blk >> 1) & (HKV - 1);
    const int b = blk >> 4;
    const int tid = threadIdx.x;
    const int w = tid >> 5;
    const int lane = tid & 31;

    const float scale = 0.08838834764831845f;
    unsigned long long q2[G][2];
#pragma unroll
    for (int g = 0; g < G; g++) {
        int h = hkv * G + g;
        float4 q = *reinterpret_cast<const float4*>(
            g_qkv + (size_t)b * NTOT + h * HD + lane * 4);
        q2[g][0] = pack2(q.x * scale, q.y * scale);
        q2[g][1] = pack2(q.z * scale, q.w * scale);
    }

    unsigned long long acc2[G][2];
#pragma unroll
    for (int g = 0; g < G; g++) { acc2[g][0] = 0ull; acc2[g][1] = 0ull; }
    float ssum = 0.f;

    auto process = [&](ulonglong2 k2, ulonglong2 v2) {
        float p[G];
#pragma unroll
        for (int g = 0; g < G; g++) {
            unsigned long long d = mul2(k2.x, q2[g][0]);
            fma2(d, k2.y, q2[g][1]);
            float2 t = unpack2(d);
            p[g] = t.x + t.y;
        }
#pragma unroll
        for (int g = 0; g < G; g++) p[g] += __shfl_xor_sync(0xffffffffu, p[g], 16);
#pragma unroll
        for (int g = 0; g < G; g++) p[g] += __shfl_xor_sync(0xffffffffu, p[g], 8);
        float v = (lane & 16) ? ((lane & 8) ? p[3] : p[2])
                              : ((lane & 8) ? p[1] : p[0]);
        v += __shfl_xor_sync(0xffffffffu, v, 4);
        v += __shfl_xor_sync(0xffffffffu, v, 2);
        v += __shfl_xor_sync(0xffffffffu, v, 1);
        float e = __expf(v);
        ssum += e;
        float e0 = __shfl_sync(0xffffffffu, e, 0);
        float e1 = __shfl_sync(0xffffffffu, e, 8);
        float e2 = __shfl_sync(0xffffffffu, e, 16);
        float e3 = __shfl_sync(0xffffffffu, e, 24);
        unsigned long long d0 = pack2(e0, e0), d1 = pack2(e1, e1);
        unsigned long long d2 = pack2(e2, e2), d3 = pack2(e3, e3);
        fma2(acc2[0][0], d0, v2.x); fma2(acc2[0][1], d0, v2.y);
        fma2(acc2[1][0], d1, v2.x); fma2(acc2[1][1], d1, v2.y);
        fma2(acc2[2][0], d2, v2.x); fma2(acc2[2][1], d2, v2.y);
        fma2(acc2[3][0], d3, v2.x); fma2(acc2[3][1], d3, v2.y);
    };

    const size_t bh = (size_t)(b * HKV + hkv) * L * HD;
    const int base = split * (L / NSPLIT) + w;
    const bool last_warp = (split == NSPLIT - 1) && (w == 7);
    const int niter = last_warp ? (L / NSPLIT / 8 - 1) : (L / NSPLIT / 8);

    const float* kcur = cache_k + bh + (size_t)base * HD + 4 * lane;
    const float* vcur = cache_v + bh + (size_t)base * HD + 4 * lane;

    for (int i = 0; i < niter; i++) {
        ulonglong2 k2 = *reinterpret_cast<const ulonglong2*>(kcur);
        ulonglong2 v2 = *reinterpret_cast<const ulonglong2*>(vcur);
        kcur += 8 * HD;
        vcur += 8 * HD;
        process(k2, v2);
    }
    if (last_warp) {
        ulonglong2 k2 = *reinterpret_cast<const ulonglong2*>(
            g_qkv + (size_t)b * NTOT + NQ + hkv * HD + 4 * lane);
        ulonglong2 v2 = *reinterpret_cast<const ulonglong2*>(
            g_qkv + (size_t)b * NTOT + NQ + NKV + hkv * HD + 4 * lane);
        process(k2, v2);
    }

    __shared__ __align__(16) float sm_acc[8][G * HD];
    __shared__ float sm_s[8][G];
#pragma unroll
    for (int g = 0; g < G; g++) {
        float2 lo = unpack2(acc2[g][0]);
        float2 hi = unpack2(acc2[g][1]);
        float4 o;
        o.x = lo.x; o.y = lo.y; o.z = hi.x; o.w = hi.y;
        *reinterpret_cast<float4*>(&sm_acc[w][g * HD + lane * 4]) = o;
    }
    if ((lane & 7) == 0) sm_s[w][lane >> 3] = ssum;
    __syncthreads();

    for (int e = tid; e < G * HD; e += 256) {
        float v = 0.f;
#pragma unroll
        for (int ww = 0; ww < 8; ww++) v += sm_acc[ww][e];
        g_att_part[(size_t)blk * (G * HD) + e] = v;
    }
    if (tid < G) {
        float v = 0.f;
#pragma unroll
        for (int ww = 0; ww < 8; ww++) v += sm_s[ww][tid];
        g_att_s[blk * G + tid] = v;
    }
}

__global__ void __launch_bounds__(128)
attn_combine_kernel()
{
    const int p = blockIdx.x;           // b*HKV + hkv
    const int b = p >> 3;
    const int hkv = p & (HKV - 1);
    const int t = threadIdx.x;
    const int g = t >> 5;
    float4 v = make_float4(0.f, 0.f, 0.f, 0.f);
    float s = 0.f;
#pragma unroll
    for (int sp = 0; sp < NSPLIT; sp++) {
        int blk = p * NSPLIT + sp;
        float4 a = *reinterpret_cast<const float4*>(
            g_att_part + (size_t)blk * (G * HD) + t * 4);
        v.x += a.x; v.y += a.y; v.z += a.z; v.w += a.w;
        s += g_att_s[blk * G + g];
    }
    float inv = 1.f / s;
    v.x *= inv; v.y *= inv; v.z *= inv; v.w *= inv;
    *reinterpret_cast<float4*>(g_attn + (size_t)b * NQ + hkv * (G * HD) + t * 4) = v;
}

__global__ void __launch_bounds__(256)
out_reduce_kernel(float* __restrict__ out)
{
    int idx = blockIdx.x * blockDim.x + threadIdx.x;
    float4 v = make_float4(0.f, 0.f, 0.f, 0.f);
#pragma unroll
    for (int s = 0; s < KSPLIT; s++) {
        float4 a = *reinterpret_cast<const float4*>(
            g_out_part + (size_t)s * B * D + idx * 4);
        v.x += a.x; v.y += a.y; v.z += a.z; v.w += a.w;
    }
    *reinterpret_cast<float4*>(out + (size_t)idx * 4) = v;
}

// -------------------- launch (attn at index 3 for the profiler) -------------
extern "C" void kernel_launch(void* const* d_in, const int* in_sizes, int n_in,
                              void* d_out, int out_size)
{
    const float* x  = (const float*)d_in[0];
    const float* ck = (const float*)d_in[1];
    const float* cv = (const float*)d_in[2];
    const float* wq = (const float*)d_in[3];
    const float* wk = (const float*)d_in[4];
    const float* wv = (const float*)d_in[5];
    const float* wo = (const float*)d_in[6];
    const float* fc = (const float*)d_in[7];
    const float* fs = (const float*)d_in[8];
    float* out = (float*)d_out;

    dim3 gq(NTOT / 128, KSPLIT);
    gemm_qkv_kernel<<<gq, 256>>>(x, wq, wk, wv);                   // idx 0

    const int HALF = B * (NTOT / 4) / 2;
    rope_reduce_kernel<<<HALF / 256, 256>>>(fc, fs, 0);            // idx 1
    rope_reduce_kernel<<<HALF / 256, 256>>>(fc, fs, 1);            // idx 2

    attn_kernel<<<B * HKV * NSPLIT, 256>>>(ck, cv);                // idx 3 (profiled)

    attn_combine_kernel<<<B * HKV, 128>>>();                       // idx 4

    dim3 gw(D / 128, KSPLIT);
    gemm_wo_kernel<<<gw, 256>>>(wo);                               // idx 5

    out_reduce_kernel<<<(B * D / 4) / 256, 256>>>(out);            // idx 6
}

// round 5
// speedup vs baseline: 1.1538x; 1.0535x over previous
#include <cuda_runtime.h>
#include <cstdint>

#define B   32
#define HKV 8
#define G   4
#define HD  128
#define D   4096
#define NQ  4096
#define NKV 1024
#define NTOT 6144
#define L   2048
#define KSPLIT 8
#define NSPLIT 4

__device__ float g_qkv_part[KSPLIT * B * NTOT];
__device__ float g_qkv[B * NTOT];
__device__ float g_att_part[B * HKV * NSPLIT * G * HD];
__device__ float g_att_s[B * HKV * NSPLIT * G];
__device__ float g_attn[B * NQ];
__device__ float g_out_part[KSPLIT * B * D];

// -------------------- f32x2 packed helpers --------------------
__device__ __forceinline__ unsigned long long pack2(float lo, float hi) {
    unsigned long long r;
    asm("mov.b64 %0, {%1, %2};" : "=l"(r) : "f"(lo), "f"(hi));
    return r;
}
__device__ __forceinline__ unsigned long long mul2(unsigned long long a,
                                                   unsigned long long b) {
    unsigned long long r;
    asm("mul.rn.f32x2 %0, %1, %2;" : "=l"(r) : "l"(a), "l"(b));
    return r;
}
__device__ __forceinline__ void fma2(unsigned long long& acc, unsigned long long a,
                                     unsigned long long b) {
    asm("fma.rn.f32x2 %0, %1, %2, %0;" : "+l"(acc) : "l"(a), "l"(b));
}
__device__ __forceinline__ float2 unpack2(unsigned long long v) {
    float2 f;
    asm("mov.b64 {%0, %1}, %2;" : "=f"(f.x), "=f"(f.y) : "l"(v));
    return f;
}

// -------------------- double-buffered GEMM core (unchanged) ----------
__device__ __forceinline__ void gemm_core(
    const float* __restrict__ A,
    const float* __restrict__ W,
    int ldw, int wc0,
    float* __restrict__ C, int ldc,
    int k0)
{
    __shared__ __align__(16) float2 As2[2][32][34];
    __shared__ __align__(16) float  Ws[2][32][132];

    const int tid = threadIdx.x;
    const int tx = tid & 31;
    const int ty = tid >> 5;

    const int a_b = tid >> 3;
    const int a_k = (tid & 7) << 2;
    const int w_r = tid >> 3;
    const int w_c = (tid & 7) << 2;

    unsigned long long acc[4][2];
#pragma unroll
    for (int r = 0; r < 4; r++) { acc[r][0] = 0ull; acc[r][1] = 0ull; }

    float4 av = *reinterpret_cast<const float4*>(A + a_b * 4096 + k0 + a_k);
    const float* wrow = W + (size_t)(k0 + w_r) * ldw + wc0 + w_c;
    float4 w0 = *reinterpret_cast<const float4*>(wrow);
    float4 w1 = *reinterpret_cast<const float4*>(wrow + 32);
    float4 w2 = *reinterpret_cast<const float4*>(wrow + 64);
    float4 w3 = *reinterpret_cast<const float4*>(wrow + 96);
    As2[0][a_k + 0][a_b] = make_float2(av.x, av.x);
    As2[0][a_k + 1][a_b] = make_float2(av.y, av.y);
    As2[0][a_k + 2][a_b] = make_float2(av.z, av.z);
    As2[0][a_k + 3][a_b] = make_float2(av.w, av.w);
    *reinterpret_cast<float4*>(&Ws[0][w_r][w_c])      = w0;
    *reinterpret_cast<float4*>(&Ws[0][w_r][w_c + 32]) = w1;
    *reinterpret_cast<float4*>(&Ws[0][w_r][w_c + 64]) = w2;
    *reinterpret_cast<float4*>(&Ws[0][w_r][w_c + 96]) = w3;
    __syncthreads();

    for (int kt = 0; kt < 16; kt++) {
        const int cur = kt & 1;
        float4 av2 = make_float4(0.f, 0.f, 0.f, 0.f);
        float4 w0n = av2, w1n = av2, w2n = av2, w3n = av2;
        if (kt < 15) {
            const int kg = k0 + (kt + 1) * 32;
            av2 = *reinterpret_cast<const float4*>(A + a_b * 4096 + kg + a_k);
            const float* wr2 = W + (size_t)(kg + w_r) * ldw + wc0 + w_c;
            w0n = *reinterpret_cast<const float4*>(wr2);
            w1n = *reinterpret_cast<const float4*>(wr2 + 32);
            w2n = *reinterpret_cast<const float4*>(wr2 + 64);
            w3n = *reinterpret_cast<const float4*>(wr2 + 96);
        }

#pragma unroll
        for (int k = 0; k < 32; k++) {
            ulonglong2 bv  = *reinterpret_cast<const ulonglong2*>(&Ws[cur][k][tx << 2]);
            ulonglong2 a01 = *reinterpret_cast<const ulonglong2*>(&As2[cur][k][ty << 2]);
            ulonglong2 a23 = *reinterpret_cast<const ulonglong2*>(&As2[cur][k][(ty << 2) + 2]);
            fma2(acc[0][0], a01.x, bv.x); fma2(acc[0][1], a01.x, bv.y);
            fma2(acc[1][0], a01.y, bv.x); fma2(acc[1][1], a01.y, bv.y);
            fma2(acc[2][0], a23.x, bv.x); fma2(acc[2][1], a23.x, bv.y);
            fma2(acc[3][0], a23.y, bv.x); fma2(acc[3][1], a23.y, bv.y);
        }

        if (kt < 15) {
            const int nb = cur ^ 1;
            As2[nb][a_k + 0][a_b] = make_float2(av2.x, av2.x);
            As2[nb][a_k + 1][a_b] = make_float2(av2.y, av2.y);
            As2[nb][a_k + 2][a_b] = make_float2(av2.z, av2.z);
            As2[nb][a_k + 3][a_b] = make_float2(av2.w, av2.w);
            *reinterpret_cast<float4*>(&Ws[nb][w_r][w_c])      = w0n;
            *reinterpret_cast<float4*>(&Ws[nb][w_r][w_c + 32]) = w1n;
            *reinterpret_cast<float4*>(&Ws[nb][w_r][w_c + 64]) = w2n;
            *reinterpret_cast<float4*>(&Ws[nb][w_r][w_c + 96]) = w3n;
        }
        __syncthreads();
    }

#pragma unroll
    for (int r = 0; r < 4; r++) {
        float2 lo = unpack2(acc[r][0]);
        float2 hi = unpack2(acc[r][1]);
        float4 o;
        o.x = lo.x; o.y = lo.y; o.z = hi.x; o.w = hi.y;
        *reinterpret_cast<float4*>(C + (size_t)((ty << 2) + r) * ldc + (tx << 2)) = o;
    }
}

__global__ void __launch_bounds__(256)
gemm_qkv_kernel(const float* __restrict__ x, const float* __restrict__ wq,
                const float* __restrict__ wk, const float* __restrict__ wv)
{
    const int col0 = blockIdx.x << 7;
    const int ks = blockIdx.y;
    const float* W; int ldw, wc0;
    if (col0 < NQ)            { W = wq; ldw = NQ;  wc0 = col0; }
    else if (col0 < NQ + NKV) { W = wk; ldw = NKV; wc0 = col0 - NQ; }
    else                      { W = wv; ldw = NKV; wc0 = col0 - NQ - NKV; }
    gemm_core(x, W, ldw, wc0,
              g_qkv_part + (size_t)ks * B * NTOT + col0, NTOT, ks * 512);
}

__global__ void __launch_bounds__(256)
gemm_wo_kernel(const float* __restrict__ wo)
{
    const int col0 = blockIdx.x << 7;
    const int ks = blockIdx.y;
    gemm_core(g_attn, wo, D, col0,
              g_out_part + (size_t)ks * B * D + col0, D, ks * 512);
}

// -------------------- split-K reduce + RoPE --------------------
__global__ void __launch_bounds__(256)
rope_reduce_kernel(const float* __restrict__ fc, const float* __restrict__ fs,
                   int part)
{
    const int HALF = B * (NTOT / 4) / 2;
    int idx = part * HALF + blockIdx.x * blockDim.x + threadIdx.x;
    int b = idx / (NTOT / 4);
    int col = (idx - b * (NTOT / 4)) * 4;
    const float* p = g_qkv_part + (size_t)b * NTOT + col;
    float4 e = make_float4(0.f, 0.f, 0.f, 0.f);
#pragma unroll
    for (int s = 0; s < KSPLIT; s++) {
        float4 a = *reinterpret_cast<const float4*>(p + (size_t)s * B * NTOT);
        e.x += a.x; e.y += a.y; e.z += a.z; e.w += a.w;
    }
    if (col < NQ + NKV) {
        int i = (col & (HD - 1)) >> 1;
        float c0 = fc[i], s0 = fs[i];
        float c1 = fc[i + 1], s1 = fs[i + 1];
        float4 r;
        r.x = e.x * c0 - e.y * s0;
        r.y = e.x * s0 + e.y * c0;
        r.z = e.z * c1 - e.w * s1;
        r.w = e.z * s1 + e.w * c1;
        e = r;
    }
    *reinterpret_cast<float4*>(g_qkv + (size_t)b * NTOT + col) = e;
}

// -------------------- attention: pair-unrolled, depth-1 pipelined ------------
// grid = B*HKV*NSPLIT (1024). Warp-per-key; lane owns dims 4L..4L+3.
// Each iteration prefetches the NEXT key pair (4x LDG.128 = 2KB in flight),
// then processes the current pair with the cheap select-reduce (1 exp/lane).
__global__ void __launch_bounds__(256, 3)
attn_kernel(const float* __restrict__ cache_k, const float* __restrict__ cache_v)
{
    const int blk = blockIdx.x;
    const int split = blk & (NSPLIT - 1);
    const int hkv = (blk >> 2) & (HKV - 1);
    const int b = blk >> 5;
    const int tid = threadIdx.x;
    const int w = tid >> 5;
    const int lane = tid & 31;

    const float scale = 0.08838834764831845f;
    unsigned long long q2[G][2];
#pragma unroll
    for (int g = 0; g < G; g++) {
        int h = hkv * G + g;
        float4 q = *reinterpret_cast<const float4*>(
            g_qkv + (size_t)b * NTOT + h * HD + lane * 4);
        q2[g][0] = pack2(q.x * scale, q.y * scale);
        q2[g][1] = pack2(q.z * scale, q.w * scale);
    }

    unsigned long long acc2[G][2];
#pragma unroll
    for (int g = 0; g < G; g++) { acc2[g][0] = 0ull; acc2[g][1] = 0ull; }
    float ssum = 0.f;

    auto process = [&](ulonglong2 k2, ulonglong2 v2) {
        float p[G];
#pragma unroll
        for (int g = 0; g < G; g++) {
            unsigned long long d = mul2(k2.x, q2[g][0]);
            fma2(d, k2.y, q2[g][1]);
            float2 t = unpack2(d);
            p[g] = t.x + t.y;
        }
#pragma unroll
        for (int g = 0; g < G; g++) p[g] += __shfl_xor_sync(0xffffffffu, p[g], 16);
#pragma unroll
        for (int g = 0; g < G; g++) p[g] += __shfl_xor_sync(0xffffffffu, p[g], 8);
        float v = (lane & 16) ? ((lane & 8) ? p[3] : p[2])
                              : ((lane & 8) ? p[1] : p[0]);
        v += __shfl_xor_sync(0xffffffffu, v, 4);
        v += __shfl_xor_sync(0xffffffffu, v, 2);
        v += __shfl_xor_sync(0xffffffffu, v, 1);
        float e = __expf(v);
        ssum += e;
        float e0 = __shfl_sync(0xffffffffu, e, 0);
        float e1 = __shfl_sync(0xffffffffu, e, 8);
        float e2 = __shfl_sync(0xffffffffu, e, 16);
        float e3 = __shfl_sync(0xffffffffu, e, 24);
        unsigned long long d0 = pack2(e0, e0), d1 = pack2(e1, e1);
        unsigned long long d2 = pack2(e2, e2), d3 = pack2(e3, e3);
        fma2(acc2[0][0], d0, v2.x); fma2(acc2[0][1], d0, v2.y);
        fma2(acc2[1][0], d1, v2.x); fma2(acc2[1][1], d1, v2.y);
        fma2(acc2[2][0], d2, v2.x); fma2(acc2[2][1], d2, v2.y);
        fma2(acc2[3][0], d3, v2.x); fma2(acc2[3][1], d3, v2.y);
    };

    const size_t bh = (size_t)(b * HKV + hkv) * L * HD;
    const int base = split * (L / NSPLIT) + w;           // L/NSPLIT = 512 keys
    const bool last_warp = (split == NSPLIT - 1) && (w == 7);
    const int niter = last_warp ? 63 : 64;               // keys for this warp
    const int npairs = niter >> 1;                       // 31 or 32
    const bool rem = (niter & 1) != 0;

    const float* kcur = cache_k + bh + (size_t)base * HD + 4 * lane;
    const float* vcur = cache_v + bh + (size_t)base * HD + 4 * lane;

    // preload pair 0 (keys j=0 and j=1, stride 8 keys apart)
    ulonglong2 ka = *reinterpret_cast<const ulonglong2*>(kcur);
    ulonglong2 va = *reinterpret_cast<const ulonglong2*>(vcur);
    ulonglong2 kb = *reinterpret_cast<const ulonglong2*>(kcur + 8 * HD);
    ulonglong2 vb = *reinterpret_cast<const ulonglong2*>(vcur + 8 * HD);

    for (int p = 0; p < npairs - 1; p++) {
        kcur += 16 * HD;
        vcur += 16 * HD;
        ulonglong2 kna = *reinterpret_cast<const ulonglong2*>(kcur);
        ulonglong2 vna = *reinterpret_cast<const ulonglong2*>(vcur);
        ulonglong2 knb = *reinterpret_cast<const ulonglong2*>(kcur + 8 * HD);
        ulonglong2 vnb = *reinterpret_cast<const ulonglong2*>(vcur + 8 * HD);
        process(ka, va);
        process(kb, vb);
        ka = kna; va = vna; kb = knb; vb = vnb;
    }
    process(ka, va);
    process(kb, vb);
    kcur += 16 * HD;
    vcur += 16 * HD;

    if (rem) {   // last_warp: leftover cached key j=62
        ulonglong2 k2 = *reinterpret_cast<const ulonglong2*>(kcur);
        ulonglong2 v2 = *reinterpret_cast<const ulonglong2*>(vcur);
        process(k2, v2);
    }
    if (last_warp) {   // new key/value at position 2047
        ulonglong2 k2 = *reinterpret_cast<const ulonglong2*>(
            g_qkv + (size_t)b * NTOT + NQ + hkv * HD + 4 * lane);
        ulonglong2 v2 = *reinterpret_cast<const ulonglong2*>(
            g_qkv + (size_t)b * NTOT + NQ + NKV + hkv * HD + 4 * lane);
        process(k2, v2);
    }

    __shared__ __align__(16) float sm_acc[8][G * HD];
    __shared__ float sm_s[8][G];
#pragma unroll
    for (int g = 0; g < G; g++) {
        float2 lo = unpack2(acc2[g][0]);
        float2 hi = unpack2(acc2[g][1]);
        float4 o;
        o.x = lo.x; o.y = lo.y; o.z = hi.x; o.w = hi.y;
        *reinterpret_cast<float4*>(&sm_acc[w][g * HD + lane * 4]) = o;
    }
    if ((lane & 7) == 0) sm_s[w][lane >> 3] = ssum;
    __syncthreads();

    for (int e = tid; e < G * HD; e += 256) {
        float v = 0.f;
#pragma unroll
        for (int ww = 0; ww < 8; ww++) v += sm_acc[ww][e];
        g_att_part[(size_t)blk * (G * HD) + e] = v;
    }
    if (tid < G) {
        float v = 0.f;
#pragma unroll
        for (int ww = 0; ww < 8; ww++) v += sm_s[ww][tid];
        g_att_s[blk * G + tid] = v;
    }
}

__global__ void __launch_bounds__(128)
attn_combine_kernel()
{
    const int p = blockIdx.x;           // b*HKV + hkv
    const int b = p >> 3;
    const int hkv = p & (HKV - 1);
    const int t = threadIdx.x;
    const int g = t >> 5;
    float4 v = make_float4(0.f, 0.f, 0.f, 0.f);
    float s = 0.f;
#pragma unroll
    for (int sp = 0; sp < NSPLIT; sp++) {
        int blk = p * NSPLIT + sp;
        float4 a = *reinterpret_cast<const float4*>(
            g_att_part + (size_t)blk * (G * HD) + t * 4);
        v.x += a.x; v.y += a.y; v.z += a.z; v.w += a.w;
        s += g_att_s[blk * G + g];
    }
    float inv = 1.f / s;
    v.x *= inv; v.y *= inv; v.z *= inv; v.w *= inv;
    *reinterpret_cast<float4*>(g_attn + (size_t)b * NQ + hkv * (G * HD) + t * 4) = v;
}

__global__ void __launch_bounds__(256)
out_reduce_kernel(float* __restrict__ out)
{
    int idx = blockIdx.x * blockDim.x + threadIdx.x;
    float4 v = make_float4(0.f, 0.f, 0.f, 0.f);
#pragma unroll
    for (int s = 0; s < KSPLIT; s++) {
        float4 a = *reinterpret_cast<const float4*>(
            g_out_part + (size_t)s * B * D + idx * 4);
        v.x += a.x; v.y += a.y; v.z += a.z; v.w += a.w;
    }
    *reinterpret_cast<float4*>(out + (size_t)idx * 4) = v;
}

// -------------------- launch (attn at index 3 for the profiler) -------------
extern "C" void kernel_launch(void* const* d_in, const int* in_sizes, int n_in,
                              void* d_out, int out_size)
{
    const float* x  = (const float*)d_in[0];
    const float* ck = (const float*)d_in[1];
    const float* cv = (const float*)d_in[2];
    const float* wq = (const float*)d_in[3];
    const float* wk = (const float*)d_in[4];
    const float* wv = (const float*)d_in[5];
    const float* wo = (const float*)d_in[6];
    const float* fc = (const float*)d_in[7];
    const float* fs = (const float*)d_in[8];
    float* out = (float*)d_out;

    dim3 gq(NTOT / 128, KSPLIT);
    gemm_qkv_kernel<<<gq, 256>>>(x, wq, wk, wv);                   // idx 0

    const int HALF = B * (NTOT / 4) / 2;
    rope_reduce_kernel<<<HALF / 256, 256>>>(fc, fs, 0);            // idx 1
    rope_reduce_kernel<<<HALF / 256, 256>>>(fc, fs, 1);            // idx 2

    attn_kernel<<<B * HKV * NSPLIT, 256>>>(ck, cv);                // idx 3 (profiled)

    attn_combine_kernel<<<B * HKV, 128>>>();                       // idx 4

    dim3 gw(D / 128, KSPLIT);
    gemm_wo_kernel<<<gw, 256>>>(wo);                               // idx 5

    out_reduce_kernel<<<(B * D / 4) / 256, 256>>>(out);            // idx 6
}